// round 1
// baseline (speedup 1.0000x reference)
#include <cuda_runtime.h>
#include <cuda_bf16.h>
#include <math.h>

#define NUM_CLASSES 13
#define C1 (NUM_CLASSES + 1)          // 14
#define B_  32
#define T_  1000
#define NQ  50
#define ROWS (B_ * T_ * NQ)           // 1,600,000
#define W_CLASS 1.0
#define W_DOA   2.0

// global accumulators: [0]=sum(w*ce), [1]=sum|diff| over matched, [2]=matched count
__device__ double g_acc[3];

__global__ void zero_acc_kernel() {
    if (threadIdx.x < 3) g_acc[threadIdx.x] = 0.0;
}

__global__ __launch_bounds__(256)
void loss_main_kernel(const float* __restrict__ pred_logits,
                      const float* __restrict__ pred_doa,
                      const float* __restrict__ target_doa,
                      const float* __restrict__ empty_weight,
                      const int*   __restrict__ target_classes) {
    int row = blockIdx.x * blockDim.x + threadIdx.x;

    float ce_w = 0.0f;
    float asum = 0.0f;
    float cnt  = 0.0f;

    if (row < ROWS) {
        // ---- classification CE ----
        const float2* lp = reinterpret_cast<const float2*>(pred_logits + (size_t)row * C1);
        float v[C1];
        #pragma unroll
        for (int j = 0; j < C1 / 2; j++) {
            float2 p = __ldg(lp + j);
            v[2 * j]     = p.x;
            v[2 * j + 1] = p.y;
        }
        int tgt = __ldg(target_classes + row);

        float m = v[0];
        #pragma unroll
        for (int j = 1; j < C1; j++) m = fmaxf(m, v[j]);
        float s = 0.0f;
        #pragma unroll
        for (int j = 0; j < C1; j++) s += expf(v[j] - m);
        float ce = logf(s) + m - v[tgt];
        ce_w = __ldg(empty_weight + tgt) * ce;

        // ---- DOA L1 over matched slots ----
        if (tgt != NUM_CLASSES) {
            size_t dbase = (size_t)row * 3;
            float p0 = __ldg(pred_doa + dbase + 0);
            float p1 = __ldg(pred_doa + dbase + 1);
            float p2 = __ldg(pred_doa + dbase + 2);
            float t0 = __ldg(target_doa + dbase + 0);
            float t1 = __ldg(target_doa + dbase + 1);
            float t2 = __ldg(target_doa + dbase + 2);
            asum = fabsf(p0 - t0) + fabsf(p1 - t1) + fabsf(p2 - t2);
            cnt  = 1.0f;
        }
    }

    // ---- block reduction: warp shuffle, then shared across warps ----
    #pragma unroll
    for (int off = 16; off > 0; off >>= 1) {
        ce_w += __shfl_down_sync(0xFFFFFFFFu, ce_w, off);
        asum += __shfl_down_sync(0xFFFFFFFFu, asum, off);
        cnt  += __shfl_down_sync(0xFFFFFFFFu, cnt,  off);
    }

    __shared__ float s_ce[8], s_ab[8], s_ct[8];
    int lane = threadIdx.x & 31;
    int wid  = threadIdx.x >> 5;
    if (lane == 0) { s_ce[wid] = ce_w; s_ab[wid] = asum; s_ct[wid] = cnt; }
    __syncthreads();

    if (wid == 0) {
        ce_w = (lane < 8) ? s_ce[lane] : 0.0f;
        asum = (lane < 8) ? s_ab[lane] : 0.0f;
        cnt  = (lane < 8) ? s_ct[lane] : 0.0f;
        #pragma unroll
        for (int off = 4; off > 0; off >>= 1) {
            ce_w += __shfl_down_sync(0xFFFFFFFFu, ce_w, off);
            asum += __shfl_down_sync(0xFFFFFFFFu, asum, off);
            cnt  += __shfl_down_sync(0xFFFFFFFFu, cnt,  off);
        }
        if (lane == 0) {
            atomicAdd(&g_acc[0], (double)ce_w);
            atomicAdd(&g_acc[1], (double)asum);
            atomicAdd(&g_acc[2], (double)cnt);
        }
    }
}

__global__ void finalize_kernel(float* __restrict__ out) {
    if (threadIdx.x == 0 && blockIdx.x == 0) {
        double loss_class = g_acc[0] / (double)ROWS;
        double n_elems = g_acc[2] * 3.0;
        double loss_doa = (n_elems > 0.0) ? (g_acc[1] / fmax(n_elems, 1.0)) : 0.0;
        out[0] = (float)(W_CLASS * loss_class + W_DOA * loss_doa);
    }
}

extern "C" void kernel_launch(void* const* d_in, const int* in_sizes, int n_in,
                              void* d_out, int out_size) {
    const float* pred_logits    = (const float*)d_in[0];
    const float* pred_doa       = (const float*)d_in[1];
    const float* target_doa     = (const float*)d_in[2];
    const float* empty_weight   = (const float*)d_in[3];
    const int*   target_classes = (const int*)d_in[4];
    float* out = (float*)d_out;

    zero_acc_kernel<<<1, 32>>>();
    int threads = 256;
    int blocks = (ROWS + threads - 1) / threads;   // 6250
    loss_main_kernel<<<blocks, threads>>>(pred_logits, pred_doa, target_doa,
                                          empty_weight, target_classes);
    finalize_kernel<<<1, 32>>>(out);
}